// round 3
// baseline (speedup 1.0000x reference)
#include <cuda_runtime.h>
#include <cuda_bf16.h>
#include <math.h>

// Problem constants: n=100, h=16, w=16, f_in=8, f_out=16
#define N_NODES 100
#define PIX 256
#define FIN 8
#define FOUT 16
#define ALPHA 0.2f

#define TI 5            // i-rows per block in fused kernel
#define DST 33          // D smem stride (words) per node — conflict-free lane-j reads

// smem (floats): D_pad[100*33]=3300 | att[4 groups][TI*100*4]=8000 | adj[TI*100]=500
#define SM_D_WORDS   (N_NODES * DST)            // 3300
#define SM_ATT_WORDS (4 * TI * N_NODES * 4)     // 8000
#define SM_ADJ_WORDS (TI * N_NODES)             // 500
#define SM_WORDS     (SM_D_WORDS + SM_ATT_WORDS + SM_ADJ_WORDS)   // 11800 -> 47200B

// Device scratch
__device__ __align__(16) float g_Wh[N_NODES * PIX * FOUT];   // [j][pixel][c]  1.6MB
__device__ float g_D[N_NODES * 32];                          // [i][r*2+dy]

// packed f32x2 helpers (sm_100+)
__device__ __forceinline__ unsigned long long pack2(float lo, float hi) {
    unsigned long long r;
    asm("mov.b64 %0, {%1,%2};" : "=l"(r) : "f"(lo), "f"(hi));
    return r;
}
__device__ __forceinline__ void unpack2(float& lo, float& hi, unsigned long long v) {
    asm("mov.b64 {%0,%1}, %2;" : "=f"(lo), "=f"(hi) : "l"(v));
}
#define FMA2(d, a, b, c) asm("fma.rn.f32x2 %0, %1, %2, %3;" : "=l"(d) : "l"(a), "l"(b), "l"(c))

// ---------------------------------------------------------------------------
// Kernel 1: Wh = x @ W ; D[i,r,dy] = sum_{x,c} Wh[i,r,x,c] * a[dy*256+x*16+c]
// grid 100 (i), block 256 (pixel)
// ---------------------------------------------------------------------------
__global__ __launch_bounds__(256) void k_wh_d(const float* __restrict__ x,
                                              const float* __restrict__ W,
                                              const float* __restrict__ a)
{
    __shared__ float W_s[FIN * FOUT];
    __shared__ float a_s[512];

    const int i = blockIdx.x;
    const int p = threadIdx.x;

    if (p < FIN * FOUT) W_s[p] = W[p];
    a_s[p]       = a[p];
    a_s[p + 256] = a[p + 256];
    __syncthreads();

    const float4* xp = reinterpret_cast<const float4*>(x) + (size_t)(i * PIX + p) * 2;
    float4 x0 = xp[0];
    float4 x1 = xp[1];
    float xv[8] = {x0.x, x0.y, x0.z, x0.w, x1.x, x1.y, x1.z, x1.w};

    float wh[FOUT];
#pragma unroll
    for (int c = 0; c < FOUT; ++c) {
        float s = 0.f;
#pragma unroll
        for (int k = 0; k < FIN; ++k) s += xv[k] * W_s[k * FOUT + c];
        wh[c] = s;
    }

    float4* whp = reinterpret_cast<float4*>(g_Wh) + (size_t)(i * PIX + p) * 4;
    whp[0] = make_float4(wh[0],  wh[1],  wh[2],  wh[3]);
    whp[1] = make_float4(wh[4],  wh[5],  wh[6],  wh[7]);
    whp[2] = make_float4(wh[8],  wh[9],  wh[10], wh[11]);
    whp[3] = make_float4(wh[12], wh[13], wh[14], wh[15]);

    const int xx = p & 15;
    float pd0 = 0.f, pd1 = 0.f;
#pragma unroll
    for (int c = 0; c < FOUT; ++c) {
        pd0 += wh[c] * a_s[xx * 16 + c];
        pd1 += wh[c] * a_s[256 + xx * 16 + c];
    }
#pragma unroll
    for (int off = 8; off >= 1; off >>= 1) {
        pd0 += __shfl_xor_sync(0xffffffffu, pd0, off, 16);
        pd1 += __shfl_xor_sync(0xffffffffu, pd1, off, 16);
    }
    if (xx == 0) {
        const int y = p >> 4;
        g_D[i * 32 + 2 * y]     = pd0;
        g_D[i * 32 + 2 * y + 1] = pd1;
    }
}

// ---------------------------------------------------------------------------
// Kernel 2 (fused): per-block att recompute (softmax over j) + h' accumulation
// grid (20 i-tiles, 8 pixel-tiles), block 128: warp = c-group, lane = pixel
// ---------------------------------------------------------------------------
__global__ __launch_bounds__(128) void k_fused(const int* __restrict__ adj,
                                               float* __restrict__ out)
{
    __shared__ __align__(16) float sm[SM_WORDS];
    float* D_s   = sm;                               // padded stride 33
    float* att_s = sm + SM_D_WORDS;                  // [w][(ii*100+j)*4 + cc]
    int*   adj_s = (int*)(sm + SM_D_WORDS + SM_ATT_WORDS);

    const int tid = threadIdx.x;
    const int w   = tid >> 5;      // warp = c-group (0..3)
    const int l   = tid & 31;
    const int i0  = blockIdx.x * TI;
    const int p0  = blockIdx.y * 32;

    float* att_w = att_s + w * (TI * N_NODES * 4);

    // ---- Phase A: stage D (padded) and adj rows ----
    for (int q = tid; q < N_NODES * 32; q += 128)
        D_s[(q >> 5) * DST + (q & 31)] = g_D[q];
    for (int q = tid; q < TI * N_NODES; q += 128)
        adj_s[q] = adj[(i0 + q / N_NODES) * N_NODES + q % N_NODES];
    __syncthreads();

    // ---- Phase B: attention for rows (ii, c), c in [4w, 4w+4) ----
#pragma unroll
    for (int ii = 0; ii < TI; ++ii) {
        const float* Di   = &D_s[(i0 + ii) * DST];
        const int*   arow = &adj_s[ii * N_NODES];
#pragma unroll
        for (int cc = 0; cc < 4; ++cc) {
            const int c = (w << 2) + cc;
            float ev[4];
            float mx = -3.4e38f;
#pragma unroll
            for (int t = 0; t < 4; ++t) {
                const int j = l + 32 * t;
                if (j < N_NODES) {
                    float e;
                    if (c < 8) {
                        const int b = 16 * j + 2 * c;
                        e = Di[(b / 100) * 2] + Di[((b + 1) / 100) * 2 + 1];
                    } else {
                        const int r2 = 2 * c - 16;
                        e = D_s[j * DST + 2 * r2] + D_s[j * DST + 2 * r2 + 3];
                    }
                    e = (e > 0.f) ? e : ALPHA * e;
                    e = (arow[j] > 0) ? e : -9e15f;
                    ev[t] = e;
                    mx = fmaxf(mx, e);
                } else {
                    ev[t] = -3.4e38f;
                }
            }
#pragma unroll
            for (int off = 16; off >= 1; off >>= 1)
                mx = fmaxf(mx, __shfl_xor_sync(0xffffffffu, mx, off));

            float s = 0.f;
#pragma unroll
            for (int t = 0; t < 4; ++t) {
                const int j = l + 32 * t;
                if (j < N_NODES) {
                    ev[t] = __expf(ev[t] - mx);
                    s += ev[t];
                }
            }
#pragma unroll
            for (int off = 16; off >= 1; off >>= 1)
                s += __shfl_xor_sync(0xffffffffu, s, off);

            const float inv = 1.0f / s;
#pragma unroll
            for (int t = 0; t < 4; ++t) {
                const int j = l + 32 * t;
                if (j < N_NODES)
                    att_w[(ii * N_NODES + j) * 4 + cc] = ev[t] * inv;
            }
        }
    }
    __syncthreads();

    // ---- Phase C: h'[i0+ii, pixel, 4w..4w+4) = sum_j att * Wh  (f32x2) ----
    const int pixel = p0 + l;

    unsigned long long acc0[TI], acc1[TI];
    const unsigned long long z = pack2(0.f, 0.f);
#pragma unroll
    for (int ii = 0; ii < TI; ++ii) { acc0[ii] = z; acc1[ii] = z; }

    const ulonglong2* wh2 = reinterpret_cast<const ulonglong2*>(g_Wh);
    const ulonglong2* at2 = reinterpret_cast<const ulonglong2*>(att_w);

#pragma unroll 4
    for (int j = 0; j < N_NODES; ++j) {
        const ulonglong2 whp = wh2[(j * PIX + pixel) * 4 + w];
#pragma unroll
        for (int ii = 0; ii < TI; ++ii) {
            const ulonglong2 ap = at2[ii * N_NODES + j];   // warp-uniform broadcast
            FMA2(acc0[ii], ap.x, whp.x, acc0[ii]);
            FMA2(acc1[ii], ap.y, whp.y, acc1[ii]);
        }
    }

#pragma unroll
    for (int ii = 0; ii < TI; ++ii) {
        float f0, f1, f2, f3;
        unpack2(f0, f1, acc0[ii]);
        unpack2(f2, f3, acc1[ii]);
        reinterpret_cast<float4*>(out)[((i0 + ii) * PIX + pixel) * 4 + w] =
            make_float4(f0, f1, f2, f3);
    }
}

// ---------------------------------------------------------------------------
extern "C" void kernel_launch(void* const* d_in, const int* in_sizes, int n_in,
                              void* d_out, int out_size)
{
    const float* x   = (const float*)d_in[0];
    const int*   adj = (const int*)d_in[1];
    const float* W   = (const float*)d_in[2];
    const float* a   = (const float*)d_in[3];
    float* out = (float*)d_out;

    k_wh_d<<<N_NODES, 256>>>(x, W, a);
    dim3 g2(N_NODES / TI, PIX / 32);
    k_fused<<<g2, 128>>>(adj, out);
}

// round 5
// speedup vs baseline: 1.2926x; 1.2926x over previous
#include <cuda_runtime.h>
#include <cuda_bf16.h>
#include <math.h>

// Problem constants: n=100, h=16, w=16, f_in=8, f_out=16
#define N_NODES 100
#define PIX 256
#define FIN 8
#define FOUT 16
#define ALPHA 0.2f

// Device scratch
__device__ __align__(16) float g_Wh[N_NODES * PIX * FOUT];       // [j][pixel][c]  1.6MB
__device__ float g_D[N_NODES * 32];                              // [i][r*2+dy]
__device__ __align__(16) float g_att[N_NODES * N_NODES * FOUT];  // [i][j][c]      640KB

// packed f32x2 helpers (sm_100+)
__device__ __forceinline__ unsigned long long pack2(float lo, float hi) {
    unsigned long long r;
    asm("mov.b64 %0, {%1,%2};" : "=l"(r) : "f"(lo), "f"(hi));
    return r;
}
__device__ __forceinline__ void unpack2(float& lo, float& hi, unsigned long long v) {
    asm("mov.b64 {%0,%1}, %2;" : "=f"(lo), "=f"(hi) : "l"(v));
}
#define FMA2(d, a, b, c) asm("fma.rn.f32x2 %0, %1, %2, %3;" : "=l"(d) : "l"(a), "l"(b), "l"(c))

// ---------------------------------------------------------------------------
// Kernel 1: Wh = x @ W ; D[i,r,dy] = sum_{x,c} Wh[i,r,x,c] * a[dy*256+x*16+c]
// grid 100 (i), block 256 (pixel)
// ---------------------------------------------------------------------------
__global__ __launch_bounds__(256) void k_wh_d(const float* __restrict__ x,
                                              const float* __restrict__ W,
                                              const float* __restrict__ a)
{
    __shared__ float W_s[FIN * FOUT];
    __shared__ float a_s[512];

    const int i = blockIdx.x;
    const int p = threadIdx.x;

    if (p < FIN * FOUT) W_s[p] = W[p];
    a_s[p]       = a[p];
    a_s[p + 256] = a[p + 256];
    __syncthreads();

    const float4* xp = reinterpret_cast<const float4*>(x) + (size_t)(i * PIX + p) * 2;
    float4 x0 = xp[0];
    float4 x1 = xp[1];
    float xv[8] = {x0.x, x0.y, x0.z, x0.w, x1.x, x1.y, x1.z, x1.w};

    float wh[FOUT];
#pragma unroll
    for (int c = 0; c < FOUT; ++c) {
        float s = 0.f;
#pragma unroll
        for (int k = 0; k < FIN; ++k) s += xv[k] * W_s[k * FOUT + c];
        wh[c] = s;
    }

    float4* whp = reinterpret_cast<float4*>(g_Wh) + (size_t)(i * PIX + p) * 4;
    whp[0] = make_float4(wh[0],  wh[1],  wh[2],  wh[3]);
    whp[1] = make_float4(wh[4],  wh[5],  wh[6],  wh[7]);
    whp[2] = make_float4(wh[8],  wh[9],  wh[10], wh[11]);
    whp[3] = make_float4(wh[12], wh[13], wh[14], wh[15]);

    const int xx = p & 15;
    float pd0 = 0.f, pd1 = 0.f;
#pragma unroll
    for (int c = 0; c < FOUT; ++c) {
        pd0 += wh[c] * a_s[xx * 16 + c];
        pd1 += wh[c] * a_s[256 + xx * 16 + c];
    }
#pragma unroll
    for (int off = 8; off >= 1; off >>= 1) {
        pd0 += __shfl_xor_sync(0xffffffffu, pd0, off, 16);
        pd1 += __shfl_xor_sync(0xffffffffu, pd1, off, 16);
    }
    if (xx == 0) {
        const int y = p >> 4;
        g_D[i * 32 + 2 * y]     = pd0;
        g_D[i * 32 + 2 * y + 1] = pd1;
    }
}

// ---------------------------------------------------------------------------
// Kernel 2: e -> leakyrelu -> mask -> softmax over j -> g_att[i][j][c]
// grid 100 (i), block 512: warp = channel c, lanes cover j strided 32
// ---------------------------------------------------------------------------
__global__ __launch_bounds__(512) void k_att(const int* __restrict__ adj)
{
    __shared__ float D_i[32];

    const int i   = blockIdx.x;
    const int tid = threadIdx.x;
    const int c   = tid >> 5;
    const int l   = tid & 31;

    if (tid < 32) D_i[tid] = g_D[i * 32 + tid];
    __syncthreads();

    float ev[4];
    float mx = -3.4e38f;
#pragma unroll
    for (int t = 0; t < 4; ++t) {
        const int j = l + t * 32;
        if (j < N_NODES) {
            float e;
            if (c < 8) {
                const int b = 16 * j + 2 * c;
                e = D_i[(b / 100) * 2] + D_i[((b + 1) / 100) * 2 + 1];
            } else {
                const int r = 2 * c - 16;
                e = g_D[j * 32 + 2 * r] + g_D[j * 32 + 2 * (r + 1) + 1];
            }
            e = (e > 0.f) ? e : ALPHA * e;
            e = (adj[i * N_NODES + j] > 0) ? e : -9e15f;
            ev[t] = e;
            mx = fmaxf(mx, e);
        } else {
            ev[t] = -3.4e38f;
        }
    }
#pragma unroll
    for (int off = 16; off >= 1; off >>= 1)
        mx = fmaxf(mx, __shfl_xor_sync(0xffffffffu, mx, off));

    float s = 0.f;
#pragma unroll
    for (int t = 0; t < 4; ++t) {
        const int j = l + t * 32;
        if (j < N_NODES) {
            ev[t] = __expf(ev[t] - mx);
            s += ev[t];
        }
    }
#pragma unroll
    for (int off = 16; off >= 1; off >>= 1)
        s += __shfl_xor_sync(0xffffffffu, s, off);

    const float inv = 1.0f / s;
#pragma unroll
    for (int t = 0; t < 4; ++t) {
        const int j = l + t * 32;
        if (j < N_NODES)
            g_att[(size_t)i * (N_NODES * FOUT) + j * FOUT + c] = ev[t] * inv;
    }
}

// ---------------------------------------------------------------------------
// Kernel 3: h'[i, pixel, c] = sum_{j=0..99} att[i,j,c] * Wh[j,pixel,c]
// grid (25 i-tiles of 4, 8 pixel-tiles of 32), block 128:
//   warp = c-group (4 channels), lane = pixel-in-tile. Full j per block.
// ---------------------------------------------------------------------------
#define TI 4
__global__ __launch_bounds__(128) void k_hprime(float* __restrict__ out)
{
    __shared__ __align__(16) float att_s[TI * N_NODES * FOUT];   // 25.6KB

    const int tid = threadIdx.x;
    const int w   = tid >> 5;      // c-group 0..3
    const int l   = tid & 31;
    const int i0  = blockIdx.x * TI;
    const int p0  = blockIdx.y * 32;

    // stage att slice: 1600 float4, guarded strided copy (1600 % 128 != 0!)
    {
        float4* dst = reinterpret_cast<float4*>(att_s);
        const float4* src = reinterpret_cast<const float4*>(g_att + (size_t)i0 * N_NODES * FOUT);
#pragma unroll
        for (int q = tid; q < TI * N_NODES * 4; q += 128)
            dst[q] = src[q];
    }
    __syncthreads();

    const int pixel = p0 + l;

    unsigned long long acc0[TI], acc1[TI];
    const unsigned long long z = pack2(0.f, 0.f);
#pragma unroll
    for (int ii = 0; ii < TI; ++ii) { acc0[ii] = z; acc1[ii] = z; }

    const ulonglong2* wh2 = reinterpret_cast<const ulonglong2*>(g_Wh);
    const ulonglong2* at2 = reinterpret_cast<const ulonglong2*>(att_s);

#pragma unroll 4
    for (int j = 0; j < N_NODES; ++j) {
        const ulonglong2 whp = wh2[(j * PIX + pixel) * 4 + w];
#pragma unroll
        for (int ii = 0; ii < TI; ++ii) {
            const ulonglong2 ap = at2[(ii * N_NODES + j) * 4 + w];  // warp-uniform broadcast
            FMA2(acc0[ii], ap.x, whp.x, acc0[ii]);
            FMA2(acc1[ii], ap.y, whp.y, acc1[ii]);
        }
    }

#pragma unroll
    for (int ii = 0; ii < TI; ++ii) {
        float f0, f1, f2, f3;
        unpack2(f0, f1, acc0[ii]);
        unpack2(f2, f3, acc1[ii]);
        reinterpret_cast<float4*>(out)[((i0 + ii) * PIX + pixel) * 4 + w] =
            make_float4(f0, f1, f2, f3);
    }
}

// ---------------------------------------------------------------------------
extern "C" void kernel_launch(void* const* d_in, const int* in_sizes, int n_in,
                              void* d_out, int out_size)
{
    const float* x   = (const float*)d_in[0];
    const int*   adj = (const int*)d_in[1];
    const float* W   = (const float*)d_in[2];
    const float* a   = (const float*)d_in[3];
    float* out = (float*)d_out;

    k_wh_d<<<N_NODES, 256>>>(x, W, a);
    k_att<<<N_NODES, 512>>>(adj);
    dim3 g3(N_NODES / TI, PIX / 32);
    k_hprime<<<g3, 128>>>(out);
}